// round 2
// baseline (speedup 1.0000x reference)
#include <cuda_runtime.h>
#include <cuda_bf16.h>
#include <math.h>

// Shapes (fixed by the problem)
#define NB 6
#define HEADS 12
#define DIM 768
#define EHD 32          // per-head depth  (E = 32!)
#define HE 384          // HEADS*EHD
#define LQ 64           // query length
#define SK 512          // encoder length
#define BATCH 64
#define HID 3072        // 4*DIM
#define MQ (BATCH*LQ)   // 4096
#define MKV (BATCH*SK)  // 32768

// ------------------------- scratch (device globals; no allocs) -------------
__device__ float g_x  [MQ  * DIM];
__device__ float g_t  [MQ  * DIM];
__device__ float g_Q  [MQ  * HE];
__device__ float g_K  [MKV * HE];
__device__ float g_V  [MKV * HE];
__device__ float g_O  [MQ  * HE];
__device__ float g_H  [MQ  * HID];
__device__ float g_wq [NB * DIM * HE];
__device__ float g_wk [NB * DIM * HE];
__device__ float g_wv [NB * DIM * HE];

// ------------------------- repack [NB,H,D,E] -> [NB,D,H*E] -----------------
__global__ void repack_kernel(const float* __restrict__ w, float* __restrict__ out)
{
    int idx = blockIdx.x * blockDim.x + threadIdx.x;
    const int total = NB * DIM * HE;
    if (idx >= total) return;
    int i = idx / (DIM * HE);
    int r = idx % (DIM * HE);
    int d = r / HE;
    int n = r % HE;
    int h = n >> 5, e = n & 31;
    out[idx] = w[(((long)i * HEADS + h) * DIM + d) * EHD + e];
}

// ------------------------- x init: broadcast pos_emb -----------------------
__global__ void init_x_kernel(const float* __restrict__ pos, float* __restrict__ x)
{
    int idx = blockIdx.x * blockDim.x + threadIdx.x;
    const int total = MQ * DIM;
    if (idx >= total) return;
    int rowq = (idx / DIM) % LQ;
    int d    = idx % DIM;
    x[idx] = pos[rowq * DIM + d];
}

// ------------------------- GEMM: C = A[MxK] @ W[KxN] (+epilogue) -----------
// mode 0: plain   mode 1: exact GELU   mode 2: add residual R
#define GBM 128
#define GBN 128
#define GBK 16

__device__ __forceinline__ float gelu_exact(float v)
{
    return 0.5f * v * (1.0f + erff(v * 0.70710678118654752f));
}

__global__ void __launch_bounds__(256) gemm_kernel(
    const float* __restrict__ A, const float* __restrict__ W,
    const float* __restrict__ R, float* __restrict__ C,
    int M, int N, int K, int mode)
{
    __shared__ float As[GBK][GBM + 4];
    __shared__ float Ws[GBK][GBN];

    const int t  = threadIdx.x;
    const int bm = blockIdx.x * GBM;
    const int bn = blockIdx.y * GBN;

    const int ar = t >> 2;            // 0..63 : A tile row (and +64)
    const int ac = (t & 3) * 4;       // 0..12 : A tile col (float4)
    const int wr = t >> 5;            // 0..7  : W tile row (and +8)
    const int wc = (t & 31) * 4;      // 0..124: W tile col (float4)

    const int tm = (t >> 4) * 8;      // 0..120
    const int tn = (t & 15) * 8;      // 0..120

    float acc[8][8];
#pragma unroll
    for (int i = 0; i < 8; ++i)
#pragma unroll
        for (int j = 0; j < 8; ++j) acc[i][j] = 0.f;

    const float* Ab = A + (long)bm * K;

    for (int k0 = 0; k0 < K; k0 += GBK) {
        float4 a0 = *(const float4*)&Ab[(long)ar * K        + k0 + ac];
        float4 a1 = *(const float4*)&Ab[(long)(ar + 64) * K + k0 + ac];
        float4 w0 = *(const float4*)&W[(long)(k0 + wr) * N     + bn + wc];
        float4 w1 = *(const float4*)&W[(long)(k0 + wr + 8) * N + bn + wc];

        As[ac + 0][ar] = a0.x; As[ac + 1][ar] = a0.y;
        As[ac + 2][ar] = a0.z; As[ac + 3][ar] = a0.w;
        As[ac + 0][ar + 64] = a1.x; As[ac + 1][ar + 64] = a1.y;
        As[ac + 2][ar + 64] = a1.z; As[ac + 3][ar + 64] = a1.w;
        *(float4*)&Ws[wr][wc]     = w0;
        *(float4*)&Ws[wr + 8][wc] = w1;
        __syncthreads();

#pragma unroll
        for (int k = 0; k < GBK; ++k) {
            float a[8], b[8];
            *(float4*)&a[0] = *(const float4*)&As[k][tm];
            *(float4*)&a[4] = *(const float4*)&As[k][tm + 4];
            *(float4*)&b[0] = *(const float4*)&Ws[k][tn];
            *(float4*)&b[4] = *(const float4*)&Ws[k][tn + 4];
#pragma unroll
            for (int i = 0; i < 8; ++i)
#pragma unroll
                for (int j = 0; j < 8; ++j)
                    acc[i][j] += a[i] * b[j];
        }
        __syncthreads();
    }

#pragma unroll
    for (int i = 0; i < 8; ++i) {
        long row = bm + tm + i;
#pragma unroll
        for (int jj = 0; jj < 2; ++jj) {
            int col = bn + tn + jj * 4;
            float4 v;
            v.x = acc[i][jj * 4 + 0]; v.y = acc[i][jj * 4 + 1];
            v.z = acc[i][jj * 4 + 2]; v.w = acc[i][jj * 4 + 3];
            if (mode == 2) {
                float4 r = *(const float4*)&R[row * N + col];
                v.x += r.x; v.y += r.y; v.z += r.z; v.w += r.w;
            } else if (mode == 1) {
                v.x = gelu_exact(v.x); v.y = gelu_exact(v.y);
                v.z = gelu_exact(v.z); v.w = gelu_exact(v.w);
            }
            *(float4*)&C[row * N + col] = v;
        }
    }
}

// ------------------------- LayerNorm (row per CTA) -------------------------
__global__ void __launch_bounds__(256) ln_kernel(
    const float* __restrict__ in, const float* __restrict__ gg,
    const float* __restrict__ bb, float* __restrict__ out)
{
    const int row = blockIdx.x;
    const float* x = in + (long)row * DIM;
    const int t = threadIdx.x;

    float v0 = x[t], v1 = x[t + 256], v2 = x[t + 512];
    float s  = v0 + v1 + v2;
    float ss = v0 * v0 + v1 * v1 + v2 * v2;

    __shared__ float sh[16];
#pragma unroll
    for (int o = 16; o; o >>= 1) {
        s  += __shfl_xor_sync(0xffffffffu, s, o);
        ss += __shfl_xor_sync(0xffffffffu, ss, o);
    }
    int w = t >> 5, l = t & 31;
    if (l == 0) { sh[w] = s; sh[w + 8] = ss; }
    __syncthreads();
    s  = sh[0] + sh[1] + sh[2] + sh[3] + sh[4] + sh[5] + sh[6] + sh[7];
    ss = sh[8] + sh[9] + sh[10] + sh[11] + sh[12] + sh[13] + sh[14] + sh[15];

    const float mean = s * (1.0f / DIM);
    const float var  = ss * (1.0f / DIM) - mean * mean;
    const float inv  = rsqrtf(var + 1e-6f);

    float* o = out + (long)row * DIM;
    o[t]       = (v0 - mean) * inv * gg[t]       + bb[t];
    o[t + 256] = (v1 - mean) * inv * gg[t + 256] + bb[t + 256];
    o[t + 512] = (v2 - mean) * inv * gg[t + 512] + bb[t + 512];
}

// ------------------------- Attention: one CTA per (b,h) --------------------
// E=32 per head. smem: Q[64x33] + K/V[64x33] + P[64x516]
#define SPW 516
#define ATTN_SMEM_FLOATS (64 * 33 + 64 * 33 + 64 * SPW)
#define ATTN_SMEM_BYTES  (ATTN_SMEM_FLOATS * 4)

__global__ void __launch_bounds__(256) attn_kernel(
    const float* __restrict__ Q, const float* __restrict__ K,
    const float* __restrict__ V, float* __restrict__ O)
{
    extern __shared__ float sm[];
    float* sQ = sm;                 // [64][33]
    float* sK = sm + 64 * 33;       // [64][33]  (reused for V)
    float* sP = sm + 2 * 64 * 33;   // [64][516]

    const int t = threadIdx.x;
    const int b = blockIdx.x / HEADS;
    const int h = blockIdx.x % HEADS;
    const float scale = 0.03608439182435161f;  // 768^-0.5 (d_model**-0.5)

    const float* Qg = Q + ((long)b * LQ) * HE + h * EHD;
    const float* Kg = K + ((long)b * SK) * HE + h * EHD;
    const float* Vg = V + ((long)b * SK) * HE + h * EHD;

    // load Q tile [64][32]
    for (int idx = t; idx < 64 * 8; idx += 256) {
        int q = idx >> 3, e4 = (idx & 7) * 4;
        float4 v = *(const float4*)&Qg[(long)q * HE + e4];
        sQ[q * 33 + e4 + 0] = v.x; sQ[q * 33 + e4 + 1] = v.y;
        sQ[q * 33 + e4 + 2] = v.z; sQ[q * 33 + e4 + 3] = v.w;
    }

    // phase 1: scores = Q @ K^T * scale
    const int q0 = (t >> 4) * 4;
    const int s0 = (t & 15) * 4;
    for (int sc = 0; sc < 8; ++sc) {
        __syncthreads();
        for (int idx = t; idx < 64 * 8; idx += 256) {
            int s = idx >> 3, e4 = (idx & 7) * 4;
            float4 v = *(const float4*)&Kg[(long)(sc * 64 + s) * HE + e4];
            sK[s * 33 + e4 + 0] = v.x; sK[s * 33 + e4 + 1] = v.y;
            sK[s * 33 + e4 + 2] = v.z; sK[s * 33 + e4 + 3] = v.w;
        }
        __syncthreads();

        float acc[4][4];
#pragma unroll
        for (int i = 0; i < 4; ++i)
#pragma unroll
            for (int j = 0; j < 4; ++j) acc[i][j] = 0.f;

#pragma unroll 8
        for (int e = 0; e < EHD; ++e) {
            float qv[4], kv[4];
#pragma unroll
            for (int i = 0; i < 4; ++i) qv[i] = sQ[(q0 + i) * 33 + e];
#pragma unroll
            for (int j = 0; j < 4; ++j) kv[j] = sK[(s0 + j) * 33 + e];
#pragma unroll
            for (int i = 0; i < 4; ++i)
#pragma unroll
                for (int j = 0; j < 4; ++j)
                    acc[i][j] += qv[i] * kv[j];
        }
#pragma unroll
        for (int i = 0; i < 4; ++i)
#pragma unroll
            for (int j = 0; j < 4; ++j)
                sP[(q0 + i) * SPW + sc * 64 + s0 + j] = acc[i][j] * scale;
    }
    __syncthreads();

    // phase 2: softmax (4 threads per row)
    {
        const int q = t >> 2, part = t & 3;
        float* row = sP + q * SPW;
        const int s_lo = part * 128, s_hi = s_lo + 128;
        float mx = -1e30f;
        for (int s = s_lo; s < s_hi; ++s) mx = fmaxf(mx, row[s]);
        mx = fmaxf(mx, __shfl_xor_sync(0xffffffffu, mx, 1));
        mx = fmaxf(mx, __shfl_xor_sync(0xffffffffu, mx, 2));
        float sum = 0.f;
        for (int s = s_lo; s < s_hi; ++s) {
            float ev = __expf(row[s] - mx);
            row[s] = ev;
            sum += ev;
        }
        sum += __shfl_xor_sync(0xffffffffu, sum, 1);
        sum += __shfl_xor_sync(0xffffffffu, sum, 2);
        float inv = 1.0f / sum;
        for (int s = s_lo; s < s_hi; ++s) row[s] *= inv;
    }
    __syncthreads();

    // phase 3: O = P @ V
    {
        const int q  = t >> 2;
        const int e0 = (t & 3) * 8;
        float acc[8];
#pragma unroll
        for (int j = 0; j < 8; ++j) acc[j] = 0.f;

        for (int sc = 0; sc < 8; ++sc) {
            __syncthreads();
            for (int idx = t; idx < 64 * 8; idx += 256) {
                int s = idx >> 3, e4 = (idx & 7) * 4;
                float4 v = *(const float4*)&Vg[(long)(sc * 64 + s) * HE + e4];
                sK[s * 33 + e4 + 0] = v.x; sK[s * 33 + e4 + 1] = v.y;
                sK[s * 33 + e4 + 2] = v.z; sK[s * 33 + e4 + 3] = v.w;
            }
            __syncthreads();
#pragma unroll 4
            for (int sl = 0; sl < 64; ++sl) {
                float p = sP[q * SPW + sc * 64 + sl];
                const float* vr = &sK[sl * 33 + e0];
#pragma unroll
                for (int j = 0; j < 8; ++j)
                    acc[j] += p * vr[j];
            }
        }

        float* Og = O + ((long)b * LQ + q) * HE + h * EHD + e0;
#pragma unroll
        for (int j4 = 0; j4 < 2; ++j4) {
            float4 v;
            v.x = acc[j4 * 4 + 0]; v.y = acc[j4 * 4 + 1];
            v.z = acc[j4 * 4 + 2]; v.w = acc[j4 * 4 + 3];
            *(float4*)&Og[j4 * 4] = v;
        }
    }
}

// ------------------------- driver ------------------------------------------
extern "C" void kernel_launch(void* const* d_in, const int* in_sizes, int n_in,
                              void* d_out, int out_size)
{
    const float* enc  = (const float*)d_in[0];
    const float* pos  = (const float*)d_in[1];
    const float* wq   = (const float*)d_in[2];
    const float* wk   = (const float*)d_in[3];
    const float* wv   = (const float*)d_in[4];
    const float* wo   = (const float*)d_in[5];
    const float* ln1g = (const float*)d_in[6];
    const float* ln1b = (const float*)d_in[7];
    const float* ln2g = (const float*)d_in[8];
    const float* ln2b = (const float*)d_in[9];
    const float* w1   = (const float*)d_in[10];
    const float* w2   = (const float*)d_in[11];

    float *x, *tmp, *Qb, *Kb, *Vb, *Ob, *Hb, *wqp, *wkp, *wvp;
    cudaGetSymbolAddress((void**)&x,   g_x);
    cudaGetSymbolAddress((void**)&tmp, g_t);
    cudaGetSymbolAddress((void**)&Qb,  g_Q);
    cudaGetSymbolAddress((void**)&Kb,  g_K);
    cudaGetSymbolAddress((void**)&Vb,  g_V);
    cudaGetSymbolAddress((void**)&Ob,  g_O);
    cudaGetSymbolAddress((void**)&Hb,  g_H);
    cudaGetSymbolAddress((void**)&wqp, g_wq);
    cudaGetSymbolAddress((void**)&wkp, g_wk);
    cudaGetSymbolAddress((void**)&wvp, g_wv);

    cudaFuncSetAttribute(attn_kernel, cudaFuncAttributeMaxDynamicSharedMemorySize,
                         ATTN_SMEM_BYTES);

    const int rp_total = NB * DIM * HE;
    repack_kernel<<<(rp_total + 255) / 256, 256>>>(wq, wqp);
    repack_kernel<<<(rp_total + 255) / 256, 256>>>(wk, wkp);
    repack_kernel<<<(rp_total + 255) / 256, 256>>>(wv, wvp);
    init_x_kernel<<<(MQ * DIM + 255) / 256, 256>>>(pos, x);

    dim3 gQ  (MQ  / GBM, HE  / GBN);  // 32 x 3
    dim3 gKV (MKV / GBM, HE  / GBN);  // 256 x 3
    dim3 gO  (MQ  / GBM, DIM / GBN);  // 32 x 6
    dim3 gF1 (MQ  / GBM, HID / GBN);  // 32 x 24
    dim3 gF2 (MQ  / GBM, DIM / GBN);  // 32 x 6

    for (int i = 0; i < NB; ++i) {
        const long woff  = (long)i * DIM * HE;    // q/k/v and (transposed) o weights
        const long w1off = (long)i * DIM * HID;
        const long w2off = (long)i * HID * DIM;

        gemm_kernel<<<gQ, 256>>>(x,   wqp + woff, nullptr, Qb, MQ,  HE, DIM, 0);
        gemm_kernel<<<gKV, 256>>>(enc, wkp + woff, nullptr, Kb, MKV, HE, DIM, 0);
        gemm_kernel<<<gKV, 256>>>(enc, wvp + woff, nullptr, Vb, MKV, HE, DIM, 0);

        attn_kernel<<<BATCH * HEADS, 256, ATTN_SMEM_BYTES>>>(Qb, Kb, Vb, Ob);

        gemm_kernel<<<gO, 256>>>(Ob, wo + woff, x, tmp, MQ, DIM, HE, 2);
        ln_kernel<<<MQ, 256>>>(tmp, ln1g + i * DIM, ln1b + i * DIM, x);

        gemm_kernel<<<gF1, 256>>>(x,  w1 + w1off, nullptr, Hb, MQ, HID, DIM, 1);
        gemm_kernel<<<gF2, 256>>>(Hb, w2 + w2off, x, tmp, MQ, DIM, HID, 2);
        ln_kernel<<<MQ, 256>>>(tmp, ln2g + i * DIM, ln2b + i * DIM,
                               (i == NB - 1) ? (float*)d_out : x);
    }
}

// round 3
// speedup vs baseline: 2.2403x; 2.2403x over previous
#include <cuda_runtime.h>
#include <cuda_bf16.h>
#include <math.h>
#include <stdint.h>

// Shapes (fixed by the problem)
#define NB 6
#define HEADS 12
#define DIM 768
#define EHD 32
#define HE 384
#define LQ 64
#define SK 512
#define BATCH 64
#define HID 3072
#define MQ (BATCH*LQ)   // 4096
#define MKV (BATCH*SK)  // 32768

// ------------------------- scratch (device globals; no allocs) -------------
__device__ float g_x  [MQ  * DIM];
__device__ float g_t  [MQ  * DIM];
__device__ float g_Q  [MQ  * HE];
__device__ float g_K  [MKV * HE];
__device__ float g_V  [MKV * HE];
__device__ float g_O  [MQ  * HE];
__device__ float g_H  [MQ  * HID];

// bf16 hi/lo activations
__device__ __nv_bfloat16 g_xh [MQ * DIM],  g_xl [MQ * DIM];
__device__ __nv_bfloat16 g_eh [MKV * DIM], g_el [MKV * DIM];
__device__ __nv_bfloat16 g_Oh [MQ * HE],   g_Ol [MQ * HE];
__device__ __nv_bfloat16 g_Hh [MQ * HID],  g_Hl [MQ * HID];

// bf16 hi/lo weights, repacked to [N][K] row-major per block
__device__ __nv_bfloat16 g_wqh[NB*HE*DIM],  g_wql[NB*HE*DIM];
__device__ __nv_bfloat16 g_wkh[NB*HE*DIM],  g_wkl[NB*HE*DIM];
__device__ __nv_bfloat16 g_wvh[NB*HE*DIM],  g_wvl[NB*HE*DIM];
__device__ __nv_bfloat16 g_woh[NB*DIM*HE],  g_wol[NB*DIM*HE];
__device__ __nv_bfloat16 g_w1h[NB*HID*DIM], g_w1l[NB*HID*DIM];
__device__ __nv_bfloat16 g_w2h[NB*DIM*HID], g_w2l[NB*DIM*HID];

// ------------------------- helpers ----------------------------------------
__device__ __forceinline__ void split_bf16(float v, __nv_bfloat16& h, __nv_bfloat16& l)
{
    h = __float2bfloat16(v);
    l = __float2bfloat16(v - __bfloat162float(h));
}

__device__ __forceinline__ float gelu_exact(float v)
{
    return 0.5f * v * (1.0f + erff(v * 0.70710678118654752f));
}

// ------------------------- repack kernels ----------------------------------
// wq/wk/wv: [NB,H,D,E] -> [NB, n=h*E+e, k=d]
__global__ void repack_qkv(const float* __restrict__ w,
                           __nv_bfloat16* __restrict__ oh, __nv_bfloat16* __restrict__ ol)
{
    int idx = blockIdx.x * blockDim.x + threadIdx.x;
    const int total = NB * HE * DIM;
    if (idx >= total) return;
    int i = idx / (HE * DIM);
    int r = idx % (HE * DIM);
    int n = r / DIM, d = r % DIM;
    int h = n >> 5, e = n & 31;
    float v = w[(((long)i * HEADS + h) * DIM + d) * EHD + e];
    split_bf16(v, oh[idx], ol[idx]);
}
// wo: [NB, HE, DIM] -> [NB, n=dim, k=he]
__global__ void repack_wo(const float* __restrict__ w,
                          __nv_bfloat16* __restrict__ oh, __nv_bfloat16* __restrict__ ol)
{
    int idx = blockIdx.x * blockDim.x + threadIdx.x;
    const int total = NB * DIM * HE;
    if (idx >= total) return;
    int i = idx / (DIM * HE);
    int r = idx % (DIM * HE);
    int n = r / HE, k = r % HE;
    float v = w[((long)i * HE + k) * DIM + n];
    split_bf16(v, oh[idx], ol[idx]);
}
// ffn: [NB, Kd, Nd] -> [NB, n, k]
__global__ void repack_ffn(const float* __restrict__ w,
                           __nv_bfloat16* __restrict__ oh, __nv_bfloat16* __restrict__ ol,
                           int Kd, int Nd)
{
    int idx = blockIdx.x * blockDim.x + threadIdx.x;
    const int total = NB * Kd * Nd;
    if (idx >= total) return;
    int i = idx / (Nd * Kd);
    int r = idx % (Nd * Kd);
    int n = r / Kd, k = r % Kd;
    float v = w[((long)i * Kd + k) * Nd + n];
    split_bf16(v, oh[idx], ol[idx]);
}

// ------------------------- fp32 -> bf16 hi/lo convert -----------------------
__global__ void cvt4_kernel(const float* __restrict__ x,
                            __nv_bfloat16* __restrict__ h, __nv_bfloat16* __restrict__ l,
                            int n4)
{
    int i = blockIdx.x * blockDim.x + threadIdx.x;
    if (i >= n4) return;
    float4 v = ((const float4*)x)[i];
    __nv_bfloat16 h0,h1,h2,h3,l0,l1,l2,l3;
    split_bf16(v.x,h0,l0); split_bf16(v.y,h1,l1);
    split_bf16(v.z,h2,l2); split_bf16(v.w,h3,l3);
    __nv_bfloat162* H = (__nv_bfloat162*)(h + 4*(long)i);
    __nv_bfloat162* L = (__nv_bfloat162*)(l + 4*(long)i);
    H[0] = __halves2bfloat162(h0,h1); H[1] = __halves2bfloat162(h2,h3);
    L[0] = __halves2bfloat162(l0,l1); L[1] = __halves2bfloat162(l2,l3);
}

// ------------------------- x init: broadcast pos_emb -----------------------
__global__ void init_x_kernel(const float* __restrict__ pos, float* __restrict__ x)
{
    int idx = blockIdx.x * blockDim.x + threadIdx.x;
    const int total = MQ * DIM;
    if (idx >= total) return;
    int rowq = (idx / DIM) % LQ;
    int d    = idx % DIM;
    x[idx] = pos[rowq * DIM + d];
}

// ------------------------- tensor-core GEMM (bf16 3-split) -----------------
// C[M,N] = A[M,K] @ B[N,K]^T  in ~fp32 accuracy.
// mode 0: plain   mode 1: exact GELU   mode 2: add residual R
#define LDSS 72   // smem row stride (bf16 elems), 64 + 8 pad

__device__ __forceinline__ uint32_t smaddr(const void* p)
{
    return (uint32_t)__cvta_generic_to_shared(p);
}
__device__ __forceinline__ void ldsm4(uint32_t a[4], uint32_t addr)
{
    asm volatile("ldmatrix.sync.aligned.m8n8.x4.shared.b16 {%0,%1,%2,%3}, [%4];"
                 : "=r"(a[0]), "=r"(a[1]), "=r"(a[2]), "=r"(a[3]) : "r"(addr));
}
__device__ __forceinline__ void mma16816(float c[4], const uint32_t a[4],
                                         uint32_t b0, uint32_t b1)
{
    asm volatile(
        "mma.sync.aligned.m16n8k16.row.col.f32.bf16.bf16.f32 "
        "{%0,%1,%2,%3}, {%4,%5,%6,%7}, {%8,%9}, {%0,%1,%2,%3};"
        : "+f"(c[0]), "+f"(c[1]), "+f"(c[2]), "+f"(c[3])
        : "r"(a[0]), "r"(a[1]), "r"(a[2]), "r"(a[3]), "r"(b0), "r"(b1));
}

__global__ void __launch_bounds__(256) mma_gemm(
    const __nv_bfloat16* __restrict__ Ah, const __nv_bfloat16* __restrict__ Al,
    const __nv_bfloat16* __restrict__ Bh, const __nv_bfloat16* __restrict__ Bl,
    const float* __restrict__ R, float* __restrict__ C,
    int M, int N, int K, int mode)
{
    extern __shared__ __nv_bfloat16 smem[];
    __nv_bfloat16* sAh = smem;
    __nv_bfloat16* sAl = sAh + 128 * LDSS;
    __nv_bfloat16* sBh = sAl + 128 * LDSS;
    __nv_bfloat16* sBl = sBh + 128 * LDSS;

    const int t    = threadIdx.x;
    const int lane = t & 31;
    const int warp = t >> 5;
    const int wm   = (warp & 1) * 64;   // 2 warp-rows
    const int wn   = (warp >> 1) * 32;  // 4 warp-cols
    const long bm  = (long)blockIdx.x * 128;
    const long bn  = (long)blockIdx.y * 128;

    const int lrow = lane & 15;
    const int lcol = (lane >> 4) * 8;

    float c[4][4][4];
#pragma unroll
    for (int a = 0; a < 4; ++a)
#pragma unroll
        for (int b = 0; b < 4; ++b)
#pragma unroll
            for (int d = 0; d < 4; ++d) c[a][b][d] = 0.f;

    for (int k0 = 0; k0 < K; k0 += 64) {
#pragma unroll
        for (int it = 0; it < 4; ++it) {
            int cidx = t + it * 256;           // 0..1023
            int row  = cidx >> 3;
            int col  = (cidx & 7) * 8;
            *(uint4*)&sAh[row * LDSS + col] = *(const uint4*)&Ah[(bm + row) * K + k0 + col];
            *(uint4*)&sAl[row * LDSS + col] = *(const uint4*)&Al[(bm + row) * K + k0 + col];
            *(uint4*)&sBh[row * LDSS + col] = *(const uint4*)&Bh[(bn + row) * K + k0 + col];
            *(uint4*)&sBl[row * LDSS + col] = *(const uint4*)&Bl[(bn + row) * K + k0 + col];
        }
        __syncthreads();

#pragma unroll
        for (int kk = 0; kk < 64; kk += 16) {
            uint32_t ah[4][4], al[4][4];
#pragma unroll
            for (int mt = 0; mt < 4; ++mt) {
                int r = (wm + mt * 16 + lrow) * LDSS + kk + lcol;
                ldsm4(ah[mt], smaddr(&sAh[r]));
                ldsm4(al[mt], smaddr(&sAl[r]));
            }
#pragma unroll
            for (int ng = 0; ng < 2; ++ng) {
                uint32_t bh[4], bl[4];
                int r = (wn + ng * 16 + lrow) * LDSS + kk + lcol;
                ldsm4(bh, smaddr(&sBh[r]));
                ldsm4(bl, smaddr(&sBl[r]));
#pragma unroll
                for (int hf = 0; hf < 2; ++hf) {
                    int nt = ng * 2 + hf;
                    uint32_t b0h = bh[hf], b1h = bh[hf + 2];
                    uint32_t b0l = bl[hf], b1l = bl[hf + 2];
#pragma unroll
                    for (int mt = 0; mt < 4; ++mt) {
                        mma16816(c[mt][nt], ah[mt], b0h, b1h);
                        mma16816(c[mt][nt], ah[mt], b0l, b1l);
                        mma16816(c[mt][nt], al[mt], b0h, b1h);
                    }
                }
            }
        }
        __syncthreads();
    }

    // epilogue: thread holds c[..][0,1] at (row0, col..col+1), c[..][2,3] at row0+8
#pragma unroll
    for (int mt = 0; mt < 4; ++mt) {
        long row0 = bm + wm + mt * 16 + (lane >> 2);
#pragma unroll
        for (int nt = 0; nt < 4; ++nt) {
            int col = (int)bn + wn + nt * 8 + (lane & 3) * 2;
#pragma unroll
            for (int hfr = 0; hfr < 2; ++hfr) {
                long row = row0 + hfr * 8;
                float2 v;
                v.x = c[mt][nt][hfr * 2 + 0];
                v.y = c[mt][nt][hfr * 2 + 1];
                if (mode == 2) {
                    float2 r = *(const float2*)&R[row * N + col];
                    v.x += r.x; v.y += r.y;
                } else if (mode == 1) {
                    v.x = gelu_exact(v.x); v.y = gelu_exact(v.y);
                }
                *(float2*)&C[row * N + col] = v;
            }
        }
    }
}

// ------------------------- LayerNorm (row per CTA) -------------------------
__global__ void __launch_bounds__(256) ln_kernel(
    const float* __restrict__ in, const float* __restrict__ gg,
    const float* __restrict__ bb, float* __restrict__ out)
{
    const int row = blockIdx.x;
    const float* x = in + (long)row * DIM;
    const int t = threadIdx.x;

    float v0 = x[t], v1 = x[t + 256], v2 = x[t + 512];
    float s  = v0 + v1 + v2;
    float ss = v0 * v0 + v1 * v1 + v2 * v2;

    __shared__ float sh[16];
#pragma unroll
    for (int o = 16; o; o >>= 1) {
        s  += __shfl_xor_sync(0xffffffffu, s, o);
        ss += __shfl_xor_sync(0xffffffffu, ss, o);
    }
    int w = t >> 5, l = t & 31;
    if (l == 0) { sh[w] = s; sh[w + 8] = ss; }
    __syncthreads();
    s  = sh[0] + sh[1] + sh[2] + sh[3] + sh[4] + sh[5] + sh[6] + sh[7];
    ss = sh[8] + sh[9] + sh[10] + sh[11] + sh[12] + sh[13] + sh[14] + sh[15];

    const float mean = s * (1.0f / DIM);
    const float var  = ss * (1.0f / DIM) - mean * mean;
    const float inv  = rsqrtf(var + 1e-6f);

    float* o = out + (long)row * DIM;
    o[t]       = (v0 - mean) * inv * gg[t]       + bb[t];
    o[t + 256] = (v1 - mean) * inv * gg[t + 256] + bb[t + 256];
    o[t + 512] = (v2 - mean) * inv * gg[t + 512] + bb[t + 512];
}

// ------------------------- Attention: one CTA per (b,h) --------------------
#define SPW 516
#define ATTN_SMEM_FLOATS (64 * 33 + 64 * 33 + 64 * SPW)
#define ATTN_SMEM_BYTES  (ATTN_SMEM_FLOATS * 4)

__global__ void __launch_bounds__(256) attn_kernel(
    const float* __restrict__ Q, const float* __restrict__ K,
    const float* __restrict__ V, float* __restrict__ O)
{
    extern __shared__ float sm[];
    float* sQ = sm;                 // [64][33]
    float* sK = sm + 64 * 33;       // [64][33]  (reused for V)
    float* sP = sm + 2 * 64 * 33;   // [64][516]

    const int t = threadIdx.x;
    const int b = blockIdx.x / HEADS;
    const int h = blockIdx.x % HEADS;
    const float scale = 0.03608439182435161f;  // 768^-0.5

    const float* Qg = Q + ((long)b * LQ) * HE + h * EHD;
    const float* Kg = K + ((long)b * SK) * HE + h * EHD;
    const float* Vg = V + ((long)b * SK) * HE + h * EHD;

    for (int idx = t; idx < 64 * 8; idx += 256) {
        int q = idx >> 3, e4 = (idx & 7) * 4;
        float4 v = *(const float4*)&Qg[(long)q * HE + e4];
        sQ[q * 33 + e4 + 0] = v.x; sQ[q * 33 + e4 + 1] = v.y;
        sQ[q * 33 + e4 + 2] = v.z; sQ[q * 33 + e4 + 3] = v.w;
    }

    const int q0 = (t >> 4) * 4;
    const int s0 = (t & 15) * 4;
    for (int sc = 0; sc < 8; ++sc) {
        __syncthreads();
        for (int idx = t; idx < 64 * 8; idx += 256) {
            int s = idx >> 3, e4 = (idx & 7) * 4;
            float4 v = *(const float4*)&Kg[(long)(sc * 64 + s) * HE + e4];
            sK[s * 33 + e4 + 0] = v.x; sK[s * 33 + e4 + 1] = v.y;
            sK[s * 33 + e4 + 2] = v.z; sK[s * 33 + e4 + 3] = v.w;
        }
        __syncthreads();

        float acc[4][4];
#pragma unroll
        for (int i = 0; i < 4; ++i)
#pragma unroll
            for (int j = 0; j < 4; ++j) acc[i][j] = 0.f;

#pragma unroll 8
        for (int e = 0; e < EHD; ++e) {
            float qv[4], kv[4];
#pragma unroll
            for (int i = 0; i < 4; ++i) qv[i] = sQ[(q0 + i) * 33 + e];
#pragma unroll
            for (int j = 0; j < 4; ++j) kv[j] = sK[(s0 + j) * 33 + e];
#pragma unroll
            for (int i = 0; i < 4; ++i)
#pragma unroll
                for (int j = 0; j < 4; ++j)
                    acc[i][j] += qv[i] * kv[j];
        }
#pragma unroll
        for (int i = 0; i < 4; ++i)
#pragma unroll
            for (int j = 0; j < 4; ++j)
                sP[(q0 + i) * SPW + sc * 64 + s0 + j] = acc[i][j] * scale;
    }
    __syncthreads();

    {
        const int q = t >> 2, part = t & 3;
        float* row = sP + q * SPW;
        const int s_lo = part * 128, s_hi = s_lo + 128;
        float mx = -1e30f;
        for (int s = s_lo; s < s_hi; ++s) mx = fmaxf(mx, row[s]);
        mx = fmaxf(mx, __shfl_xor_sync(0xffffffffu, mx, 1));
        mx = fmaxf(mx, __shfl_xor_sync(0xffffffffu, mx, 2));
        float sum = 0.f;
        for (int s = s_lo; s < s_hi; ++s) {
            float ev = __expf(row[s] - mx);
            row[s] = ev;
            sum += ev;
        }
        sum += __shfl_xor_sync(0xffffffffu, sum, 1);
        sum += __shfl_xor_sync(0xffffffffu, sum, 2);
        float inv = 1.0f / sum;
        for (int s = s_lo; s < s_hi; ++s) row[s] *= inv;
    }
    __syncthreads();

    {
        const int q  = t >> 2;
        const int e0 = (t & 3) * 8;
        float acc[8];
#pragma unroll
        for (int j = 0; j < 8; ++j) acc[j] = 0.f;

        for (int sc = 0; sc < 8; ++sc) {
            __syncthreads();
            for (int idx = t; idx < 64 * 8; idx += 256) {
                int s = idx >> 3, e4 = (idx & 7) * 4;
                float4 v = *(const float4*)&Vg[(long)(sc * 64 + s) * HE + e4];
                sK[s * 33 + e4 + 0] = v.x; sK[s * 33 + e4 + 1] = v.y;
                sK[s * 33 + e4 + 2] = v.z; sK[s * 33 + e4 + 3] = v.w;
            }
            __syncthreads();
#pragma unroll 4
            for (int sl = 0; sl < 64; ++sl) {
                float p = sP[q * SPW + sc * 64 + sl];
                const float* vr = &sK[sl * 33 + e0];
#pragma unroll
                for (int j = 0; j < 8; ++j)
                    acc[j] += p * vr[j];
            }
        }

        float* Og = O + ((long)b * LQ + q) * HE + h * EHD + e0;
#pragma unroll
        for (int j4 = 0; j4 < 2; ++j4) {
            float4 v;
            v.x = acc[j4 * 4 + 0]; v.y = acc[j4 * 4 + 1];
            v.z = acc[j4 * 4 + 2]; v.w = acc[j4 * 4 + 3];
            *(float4*)&Og[j4 * 4] = v;
        }
    }
}

// ------------------------- driver ------------------------------------------
#define GEMM_SMEM (4 * 128 * LDSS * 2)

extern "C" void kernel_launch(void* const* d_in, const int* in_sizes, int n_in,
                              void* d_out, int out_size)
{
    const float* enc  = (const float*)d_in[0];
    const float* pos  = (const float*)d_in[1];
    const float* wq   = (const float*)d_in[2];
    const float* wk   = (const float*)d_in[3];
    const float* wv   = (const float*)d_in[4];
    const float* wo   = (const float*)d_in[5];
    const float* ln1g = (const float*)d_in[6];
    const float* ln1b = (const float*)d_in[7];
    const float* ln2g = (const float*)d_in[8];
    const float* ln2b = (const float*)d_in[9];
    const float* w1   = (const float*)d_in[10];
    const float* w2   = (const float*)d_in[11];

    float *x, *tmp, *Qb, *Kb, *Vb, *Ob, *Hb;
    cudaGetSymbolAddress((void**)&x,   g_x);
    cudaGetSymbolAddress((void**)&tmp, g_t);
    cudaGetSymbolAddress((void**)&Qb,  g_Q);
    cudaGetSymbolAddress((void**)&Kb,  g_K);
    cudaGetSymbolAddress((void**)&Vb,  g_V);
    cudaGetSymbolAddress((void**)&Ob,  g_O);
    cudaGetSymbolAddress((void**)&Hb,  g_H);

    __nv_bfloat16 *xh,*xl,*eh,*el,*Oh,*Ol,*Hh,*Hl;
    cudaGetSymbolAddress((void**)&xh, g_xh); cudaGetSymbolAddress((void**)&xl, g_xl);
    cudaGetSymbolAddress((void**)&eh, g_eh); cudaGetSymbolAddress((void**)&el, g_el);
    cudaGetSymbolAddress((void**)&Oh, g_Oh); cudaGetSymbolAddress((void**)&Ol, g_Ol);
    cudaGetSymbolAddress((void**)&Hh, g_Hh); cudaGetSymbolAddress((void**)&Hl, g_Hl);

    __nv_bfloat16 *wqh,*wql,*wkh,*wkl,*wvh,*wvl,*woh,*wol,*w1h,*w1l,*w2h,*w2l;
    cudaGetSymbolAddress((void**)&wqh, g_wqh); cudaGetSymbolAddress((void**)&wql, g_wql);
    cudaGetSymbolAddress((void**)&wkh, g_wkh); cudaGetSymbolAddress((void**)&wkl, g_wkl);
    cudaGetSymbolAddress((void**)&wvh, g_wvh); cudaGetSymbolAddress((void**)&wvl, g_wvl);
    cudaGetSymbolAddress((void**)&woh, g_woh); cudaGetSymbolAddress((void**)&wol, g_wol);
    cudaGetSymbolAddress((void**)&w1h, g_w1h); cudaGetSymbolAddress((void**)&w1l, g_w1l);
    cudaGetSymbolAddress((void**)&w2h, g_w2h); cudaGetSymbolAddress((void**)&w2l, g_w2l);

    cudaFuncSetAttribute(attn_kernel, cudaFuncAttributeMaxDynamicSharedMemorySize,
                         ATTN_SMEM_BYTES);
    cudaFuncSetAttribute(mma_gemm, cudaFuncAttributeMaxDynamicSharedMemorySize,
                         GEMM_SMEM);

    // weight repack + input conversions
    {
        int n = NB * HE * DIM;
        repack_qkv<<<(n + 255) / 256, 256>>>(wq, wqh, wql);
        repack_qkv<<<(n + 255) / 256, 256>>>(wk, wkh, wkl);
        repack_qkv<<<(n + 255) / 256, 256>>>(wv, wvh, wvl);
        repack_wo <<<(n + 255) / 256, 256>>>(wo, woh, wol);
        int nf = NB * DIM * HID;
        repack_ffn<<<(nf + 255) / 256, 256>>>(w1, w1h, w1l, DIM, HID);
        repack_ffn<<<(nf + 255) / 256, 256>>>(w2, w2h, w2l, HID, DIM);
    }
    init_x_kernel<<<(MQ * DIM + 255) / 256, 256>>>(pos, x);
    cvt4_kernel<<<(MKV * DIM / 4 + 255) / 256, 256>>>(enc, eh, el, MKV * DIM / 4);

    dim3 gQ  (MQ  / 128, HE  / 128);
    dim3 gKV (MKV / 128, HE  / 128);
    dim3 gO  (MQ  / 128, DIM / 128);
    dim3 gF1 (MQ  / 128, HID / 128);
    dim3 gF2 (MQ  / 128, DIM / 128);

    const int nx4 = MQ * DIM / 4;
    const int no4 = MQ * HE  / 4;
    const int nh4 = MQ * HID / 4;

    for (int i = 0; i < NB; ++i) {
        const long woff  = (long)i * DIM * HE;
        const long w1off = (long)i * DIM * HID;
        const long w2off = (long)i * HID * DIM;

        cvt4_kernel<<<(nx4 + 255) / 256, 256>>>(x, xh, xl, nx4);

        mma_gemm<<<gQ,  256, GEMM_SMEM>>>(xh, xl, wqh + woff, wql + woff,
                                          nullptr, Qb, MQ,  HE, DIM, 0);
        mma_gemm<<<gKV, 256, GEMM_SMEM>>>(eh, el, wkh + woff, wkl + woff,
                                          nullptr, Kb, MKV, HE, DIM, 0);
        mma_gemm<<<gKV, 256, GEMM_SMEM>>>(eh, el, wvh + woff, wvl + woff,
                                          nullptr, Vb, MKV, HE, DIM, 0);

        attn_kernel<<<BATCH * HEADS, 256, ATTN_SMEM_BYTES>>>(Qb, Kb, Vb, Ob);

        cvt4_kernel<<<(no4 + 255) / 256, 256>>>(Ob, Oh, Ol, no4);
        mma_gemm<<<gO, 256, GEMM_SMEM>>>(Oh, Ol, woh + woff, wol + woff,
                                         x, tmp, MQ, DIM, HE, 2);
        ln_kernel<<<MQ, 256>>>(tmp, ln1g + i * DIM, ln1b + i * DIM, x);

        cvt4_kernel<<<(nx4 + 255) / 256, 256>>>(x, xh, xl, nx4);
        mma_gemm<<<gF1, 256, GEMM_SMEM>>>(xh, xl, w1h + w1off, w1l + w1off,
                                          nullptr, Hb, MQ, HID, DIM, 1);
        cvt4_kernel<<<(nh4 + 255) / 256, 256>>>(Hb, Hh, Hl, nh4);
        mma_gemm<<<gF2, 256, GEMM_SMEM>>>(Hh, Hl, w2h + w2off, w2l + w2off,
                                          x, tmp, MQ, DIM, HID, 2);
        ln_kernel<<<MQ, 256>>>(tmp, ln2g + i * DIM, ln2b + i * DIM,
                               (i == NB - 1) ? (float*)d_out : x);
    }
}